// round 11
// baseline (speedup 1.0000x reference)
#include <cuda_runtime.h>
#include <cuda_bf16.h>
#include <cstdint>

#define MAXN 100000
#define MAXE 3200000
#define FIN  256
#define FOUT 64

// Scratch (device globals — allocation is forbidden)
__device__ float  g_h[MAXN * FOUT];   // projected features (25.6 MB, L2-resident)
__device__ float  g_as[MAXN];         // h · att_src
__device__ float  g_ad[MAXN];         // h · att_dst
__device__ int    g_cnt[MAXN];        // in-degree (zeroed by k_agg for next replay)
__device__ int    g_offs[MAXN];       // CSR offsets
__device__ int    g_bsum[512];        // scan block sums
__device__ float2 g_sp[MAXE];         // dst-sorted (src_id_bits, p)

static __device__ __forceinline__ float leaky(float v) {
    return v > 0.0f ? v : 0.2f * v;
}

// ---------------- mma.sync helpers (arch-portable sm_80+ path) --------------
static __device__ __forceinline__ uint32_t smem_u32(const void* p) {
    uint32_t a;
    asm("{ .reg .u64 t; cvta.to.shared.u64 t, %1; cvt.u32.u64 %0, t; }"
        : "=r"(a) : "l"(p));
    return a;
}
static __device__ __forceinline__ void ldsm_x4(uint32_t* r, uint32_t addr) {
    asm volatile("ldmatrix.sync.aligned.m8n8.x4.shared.b16 {%0,%1,%2,%3}, [%4];"
                 : "=r"(r[0]), "=r"(r[1]), "=r"(r[2]), "=r"(r[3]) : "r"(addr));
}
static __device__ __forceinline__ void ldsm_x4_t(uint32_t* r, uint32_t addr) {
    asm volatile("ldmatrix.sync.aligned.m8n8.x4.trans.shared.b16 {%0,%1,%2,%3}, [%4];"
                 : "=r"(r[0]), "=r"(r[1]), "=r"(r[2]), "=r"(r[3]) : "r"(addr));
}
static __device__ __forceinline__ void mma_bf16(float* c, const uint32_t* a,
                                                const uint32_t* b) {
    asm volatile(
        "mma.sync.aligned.m16n8k16.row.col.f32.bf16.bf16.f32 "
        "{%0,%1,%2,%3}, {%4,%5,%6,%7}, {%8,%9}, {%0,%1,%2,%3};"
        : "+f"(c[0]), "+f"(c[1]), "+f"(c[2]), "+f"(c[3])
        : "r"(a[0]), "r"(a[1]), "r"(a[2]), "r"(a[3]), "r"(b[0]), "r"(b[1]));
}

// SMEM layout (bytes). A chunk: 128 rows x 128 k bf16, stride 136 elems.
// B chunk: 128 k x 64 n bf16, stride 72 elems. h_s (fp32, stride 72) reuses A.
#define A_STRIDE 136
#define B_STRIDE 72
#define OFF_A_HI 0
#define OFF_A_LO (128 * A_STRIDE * 2)                 // 34816
#define OFF_B_HI (2 * 128 * A_STRIDE * 2)             // 69632
#define OFF_B_LO (OFF_B_HI + 128 * B_STRIDE * 2)      // 88064
#define SM_TOTAL (OFF_B_LO + 128 * B_STRIDE * 2)      // 106496

// ---------------------------------------------------------------------------
// K1: h = x @ W via mma.sync bf16-split (hi+lo, 3 mmas/product).
//     BM=128, BN=64, K=256 in 2 chunks of 128. 8 warps: 4(M) x 2(N),
//     each warp a 32x32 output tile (2x4 m16n8 frags).
//     Fused: in-degree histogram; epilogue h store + a_src/a_dst per row.
// ---------------------------------------------------------------------------
__global__ __launch_bounds__(256, 1) void k_gemm_mma(const float* __restrict__ x,
                                                     const float* __restrict__ W,
                                                     const float* __restrict__ att_src,
                                                     const float* __restrict__ att_dst,
                                                     const int* __restrict__ ei,
                                                     int n, int e) {
    extern __shared__ char smem[];
    const uint32_t sb = smem_u32(smem);
    const int tid  = threadIdx.x;
    const int w    = tid >> 5;
    const int lane = tid & 31;
    const int wm   = w & 3;          // M offset wm*32
    const int wn   = w >> 2;         // N offset wn*32
    const int row0 = blockIdx.x * 128;

    // ---- fused histogram: this block's slice of dst ids (REDs drain async)
    {
        int epb = (e + gridDim.x - 1) / gridDim.x;
        int e0 = blockIdx.x * epb;
        int e1 = min(e0 + epb, e);
        for (int i = e0 + tid; i < e1; i += 256)
            atomicAdd(&g_cnt[__ldg(ei + (size_t)e + i)], 1);
    }

    float acc[2][4][4];
#pragma unroll
    for (int mi = 0; mi < 2; mi++)
#pragma unroll
        for (int nj = 0; nj < 4; nj++)
#pragma unroll
            for (int q = 0; q < 4; q++) acc[mi][nj][q] = 0.0f;

    for (int kc = 0; kc < FIN; kc += 128) {
        // ---- stage A chunk: 128 rows x 128 k, bf16 hi/lo (16 float4/thread)
#pragma unroll
        for (int it = 0; it < 16; it++) {
            int idx = it * 256 + tid;          // 0..4095 float4 slots
            int r = idx >> 5, c4 = idx & 31;
            int gr = row0 + r;
            float4 v = make_float4(0.f, 0.f, 0.f, 0.f);
            if (gr < n) v = *(const float4*)(x + (size_t)gr * FIN + kc + c4 * 4);
            __nv_bfloat162 hA, hB, lA, lB;
            hA.x = __float2bfloat16_rn(v.x); hA.y = __float2bfloat16_rn(v.y);
            hB.x = __float2bfloat16_rn(v.z); hB.y = __float2bfloat16_rn(v.w);
            lA.x = __float2bfloat16_rn(v.x - __bfloat162float(hA.x));
            lA.y = __float2bfloat16_rn(v.y - __bfloat162float(hA.y));
            lB.x = __float2bfloat16_rn(v.z - __bfloat162float(hB.x));
            lB.y = __float2bfloat16_rn(v.w - __bfloat162float(hB.y));
            uint32_t boff = (uint32_t)(r * A_STRIDE + c4 * 4) * 2;
            *(uint2*)(smem + OFF_A_HI + boff) =
                make_uint2(*(uint32_t*)&hA, *(uint32_t*)&hB);
            *(uint2*)(smem + OFF_A_LO + boff) =
                make_uint2(*(uint32_t*)&lA, *(uint32_t*)&lB);
        }
        // ---- stage B chunk: 128 k x 64 n (8 float4/thread)
#pragma unroll
        for (int it = 0; it < 8; it++) {
            int idx = it * 256 + tid;          // 0..2047
            int r = idx >> 4, c4 = idx & 15;
            float4 v = *(const float4*)(W + (size_t)(kc + r) * FOUT + c4 * 4);
            __nv_bfloat162 hA, hB, lA, lB;
            hA.x = __float2bfloat16_rn(v.x); hA.y = __float2bfloat16_rn(v.y);
            hB.x = __float2bfloat16_rn(v.z); hB.y = __float2bfloat16_rn(v.w);
            lA.x = __float2bfloat16_rn(v.x - __bfloat162float(hA.x));
            lA.y = __float2bfloat16_rn(v.y - __bfloat162float(hA.y));
            lB.x = __float2bfloat16_rn(v.z - __bfloat162float(hB.x));
            lB.y = __float2bfloat16_rn(v.w - __bfloat162float(hB.y));
            uint32_t boff = (uint32_t)(r * B_STRIDE + c4 * 4) * 2;
            *(uint2*)(smem + OFF_B_HI + boff) =
                make_uint2(*(uint32_t*)&hA, *(uint32_t*)&hB);
            *(uint2*)(smem + OFF_B_LO + boff) =
                make_uint2(*(uint32_t*)&lA, *(uint32_t*)&lB);
        }
        __syncthreads();

        // ---- mma mainloop over this chunk
#pragma unroll
        for (int kk = 0; kk < 128; kk += 16) {
            uint32_t ah[2][4], al[2][4], bh[2][4], bl[2][4];
#pragma unroll
            for (int mi = 0; mi < 2; mi++) {
                int arow = wm * 32 + mi * 16 + (lane & 15);
                int acol = kk + (lane >> 4) * 8;
                uint32_t ao = (uint32_t)(arow * A_STRIDE + acol) * 2;
                ldsm_x4(ah[mi], sb + OFF_A_HI + ao);
                ldsm_x4(al[mi], sb + OFF_A_LO + ao);
            }
#pragma unroll
            for (int ng = 0; ng < 2; ng++) {
                int brow = kk + (lane & 15);
                int bcol = wn * 32 + ng * 16 + (lane >> 4) * 8;
                uint32_t bo = (uint32_t)(brow * B_STRIDE + bcol) * 2;
                ldsm_x4_t(bh[ng], sb + OFF_B_HI + bo);
                ldsm_x4_t(bl[ng], sb + OFF_B_LO + bo);
            }
#pragma unroll
            for (int mi = 0; mi < 2; mi++)
#pragma unroll
                for (int nj = 0; nj < 4; nj++) {
                    const uint32_t* bhp = &bh[nj >> 1][(nj & 1) * 2];
                    const uint32_t* blp = &bl[nj >> 1][(nj & 1) * 2];
                    mma_bf16(acc[mi][nj], ah[mi], bhp);
                    mma_bf16(acc[mi][nj], ah[mi], blp);
                    mma_bf16(acc[mi][nj], al[mi], bhp);
                }
        }
        __syncthreads();
    }

    // ---- epilogue: D frags -> smem (fp32, stride 72), then coalesced store
    float* h_s = (float*)smem;
    {
        int r = lane >> 2, c = (lane & 3) * 2;
#pragma unroll
        for (int mi = 0; mi < 2; mi++)
#pragma unroll
            for (int nj = 0; nj < 4; nj++) {
                int rs = wm * 32 + mi * 16 + r;
                int cs = wn * 32 + nj * 8 + c;
                h_s[rs * 72 + cs]           = acc[mi][nj][0];
                h_s[rs * 72 + cs + 1]       = acc[mi][nj][1];
                h_s[(rs + 8) * 72 + cs]     = acc[mi][nj][2];
                h_s[(rs + 8) * 72 + cs + 1] = acc[mi][nj][3];
            }
    }
    __syncthreads();

    // h -> gmem + as/ad per row (each warp: rows w, w+8, ..., w+120)
    float a_s0 = __ldg(att_src + lane),      a_s1 = __ldg(att_src + lane + 32);
    float a_d0 = __ldg(att_dst + lane),      a_d1 = __ldg(att_dst + lane + 32);
#pragma unroll
    for (int it = 0; it < 16; it++) {
        int rl = w + it * 8;
        int grow = row0 + rl;
        if (grow < n) {
            float v0 = h_s[rl * 72 + lane];
            float v1 = h_s[rl * 72 + lane + 32];
            g_h[(size_t)grow * FOUT + lane]      = v0;
            g_h[(size_t)grow * FOUT + lane + 32] = v1;
            float sa = v0 * a_s0 + v1 * a_s1;
            float sd = v0 * a_d0 + v1 * a_d1;
#pragma unroll
            for (int o = 16; o > 0; o >>= 1) {
                sa += __shfl_xor_sync(0xFFFFFFFFu, sa, o);
                sd += __shfl_xor_sync(0xFFFFFFFFu, sd, o);
            }
            if (lane == 0) {
                g_as[grow] = sa;
                g_ad[grow] = sd;
            }
        }
    }
}

// ---------------------------------------------------------------------------
// K2a/b/c: exclusive prefix scan over cnt -> offs
// ---------------------------------------------------------------------------
__global__ __launch_bounds__(256) void k_scan1(int n) {
    __shared__ int sh[256];
    int i = blockIdx.x * 256 + threadIdx.x;
    int v = (i < n) ? g_cnt[i] : 0;
    sh[threadIdx.x] = v;
    __syncthreads();
#pragma unroll
    for (int o = 1; o < 256; o <<= 1) {
        int t = (threadIdx.x >= o) ? sh[threadIdx.x - o] : 0;
        __syncthreads();
        sh[threadIdx.x] += t;
        __syncthreads();
    }
    if (i < n) g_offs[i] = sh[threadIdx.x] - v;
    if (threadIdx.x == 255) g_bsum[blockIdx.x] = sh[255];
}

__global__ __launch_bounds__(512) void k_scan2(int nb) {
    __shared__ int sh[512];
    int t = threadIdx.x;
    int v = (t < nb) ? g_bsum[t] : 0;
    sh[t] = v;
    __syncthreads();
#pragma unroll
    for (int o = 1; o < 512; o <<= 1) {
        int u = (t >= o) ? sh[t - o] : 0;
        __syncthreads();
        sh[t] += u;
        __syncthreads();
    }
    if (t < nb) g_bsum[t] = sh[t] - v;
}

__global__ __launch_bounds__(256) void k_scan3(int n) {
    int i = blockIdx.x * 256 + threadIdx.x;
    if (i < n) g_offs[i] += g_bsum[blockIdx.x];
}

// ---------------------------------------------------------------------------
// K3: scatter — dst-sorted packed (src, p); advances offs[d] to end.
// ---------------------------------------------------------------------------
__global__ __launch_bounds__(256) void k_scatter(const int* __restrict__ ei, int e) {
    int i = blockIdx.x * 256 + threadIdx.x;
    if (i >= e) return;
    int s = __ldg(ei + i);
    int d = __ldg(ei + e + i);
    float p = __expf(leaky(__ldg(&g_as[s]) + __ldg(&g_ad[d])));
    int pos = atomicAdd(&g_offs[d], 1);
    g_sp[pos] = make_float2(__int_as_float(s), p);
}

// ---------------------------------------------------------------------------
// K4: warp-per-dst aggregation (2 subgroups x unroll 2). Epilogue: self-loop +
//     normalize + bias; single store; zeroes g_cnt for the next replay.
// ---------------------------------------------------------------------------
__global__ __launch_bounds__(256) void k_agg(const float* __restrict__ bias,
                                             float* __restrict__ out, int n) {
    int node = (int)((blockIdx.x * 256u + threadIdx.x) >> 5);
    if (node >= n) return;
    int lane = threadIdx.x & 31;
    int sub  = lane & 15;
    int half = lane >> 4;

    int cnt   = g_cnt[node];
    int end   = g_offs[node];           // post-scatter end
    int start = end - cnt;
    if (lane == 0) g_cnt[node] = 0;     // reset for next replay's histogram

    float4 acc = make_float4(0.f, 0.f, 0.f, 0.f);
    float denl = 0.0f;

    int base = start;
    for (; base + 4 <= end; base += 4) {
        int i0 = base + half;
        int i1 = i0 + 2;
        float2 sp0 = __ldg(&g_sp[i0]);
        float2 sp1 = __ldg(&g_sp[i1]);
        int s0 = __float_as_int(sp0.x);
        int s1 = __float_as_int(sp1.x);
        const float4 h0 = *(const float4*)(g_h + (size_t)s0 * FOUT + sub * 4);
        const float4 h1 = *(const float4*)(g_h + (size_t)s1 * FOUT + sub * 4);
        acc.x += sp0.y * h0.x + sp1.y * h1.x;
        acc.y += sp0.y * h0.y + sp1.y * h1.y;
        acc.z += sp0.y * h0.z + sp1.y * h1.z;
        acc.w += sp0.y * h0.w + sp1.y * h1.w;
        if (sub == 0) denl += sp0.y + sp1.y;
    }
    for (; base < end; base += 2) {
        int i0 = base + half;
        if (i0 < end) {
            float2 sp0 = __ldg(&g_sp[i0]);
            int s0 = __float_as_int(sp0.x);
            const float4 h0 = *(const float4*)(g_h + (size_t)s0 * FOUT + sub * 4);
            acc.x += sp0.y * h0.x;
            acc.y += sp0.y * h0.y;
            acc.z += sp0.y * h0.z;
            acc.w += sp0.y * h0.w;
            if (sub == 0) denl += sp0.y;
        }
    }

    acc.x += __shfl_xor_sync(0xFFFFFFFFu, acc.x, 16);
    acc.y += __shfl_xor_sync(0xFFFFFFFFu, acc.y, 16);
    acc.z += __shfl_xor_sync(0xFFFFFFFFu, acc.z, 16);
    acc.w += __shfl_xor_sync(0xFFFFFFFFu, acc.w, 16);
    float den = __shfl_sync(0xFFFFFFFFu, denl, 0)
              + __shfl_sync(0xFFFFFFFFu, denl, 16);

    float ps  = __expf(leaky(g_as[node] + g_ad[node]));   // self-loop weight
    float inv = 1.0f / (den + ps + 1e-16f);

    if (lane < 16) {
        const float4 hi4 = *(const float4*)(g_h + (size_t)node * FOUT + sub * 4);
        const float4 b4  = *(const float4*)(bias + sub * 4);
        float4 o;
        o.x = (acc.x + ps * hi4.x) * inv + b4.x;
        o.y = (acc.y + ps * hi4.y) * inv + b4.y;
        o.z = (acc.z + ps * hi4.z) * inv + b4.z;
        o.w = (acc.w + ps * hi4.w) * inv + b4.w;
        *(float4*)(out + (size_t)node * FOUT + sub * 4) = o;
    }
}

// ---------------------------------------------------------------------------
extern "C" void kernel_launch(void* const* d_in, const int* in_sizes, int n_in,
                              void* d_out, int out_size) {
    const float* x       = (const float*)d_in[0];
    const int*   ei      = (const int*)d_in[1];
    const float* W       = (const float*)d_in[2];
    const float* att_src = (const float*)d_in[3];
    const float* att_dst = (const float*)d_in[4];
    const float* bias    = (const float*)d_in[5];
    float* out = (float*)d_out;

    const int n = in_sizes[0] / FIN;   // 100000
    const int e = in_sizes[1] / 2;     // 3200000
    const int nb = (n + 255) / 256;    // scan blocks (391 <= 512)

    static int smem_set = 0;
    if (!smem_set) {
        cudaFuncSetAttribute(k_gemm_mma,
                             cudaFuncAttributeMaxDynamicSharedMemorySize, SM_TOTAL);
        smem_set = 1;
    }

    // K1: bf16-split mma projection + attention halves + fused histogram
    k_gemm_mma<<<(n + 127) / 128, 256, SM_TOTAL>>>(x, W, att_src, att_dst, ei, n, e);
    // K2: exclusive scan cnt -> offs
    k_scan1<<<nb, 256>>>(n);
    k_scan2<<<1, 512>>>(nb);
    k_scan3<<<nb, 256>>>(n);
    // K3: dst-sorted scatter of packed (src, p)
    k_scatter<<<(e + 255) / 256, 256>>>(ei, e);
    // K4: warp-per-dst aggregation (+normalize, self-loop, bias, cnt reset)
    k_agg<<<(n + 7) / 8, 256>>>(bias, out, n);
}

// round 14
// speedup vs baseline: 1.0159x; 1.0159x over previous
#include <cuda_runtime.h>
#include <cuda_bf16.h>

#define MAXN 100000
#define MAXE 3200000
#define FIN  256
#define FOUT 64

// Scratch (device globals — allocation is forbidden)
__device__ float  g_h[MAXN * FOUT];   // projected features (25.6 MB, L2-resident)
__device__ float  g_as[MAXN];         // h · att_src
__device__ float  g_ad[MAXN];         // h · att_dst
__device__ int    g_cnt[MAXN];        // in-degree (zeroed by k_agg for next replay)
__device__ int    g_offs[MAXN];       // CSR offsets
__device__ int    g_bsum[512];        // scan block sums
__device__ float2 g_sp[MAXE];         // dst-sorted packed (src_id_bits, p)

static __device__ __forceinline__ float leaky(float v) {
    return v > 0.0f ? v : 0.2f * v;
}

// ---------------------------------------------------------------------------
// K1: h = x @ W  (scalar SGEMM, BM=128, BN=64, BK=16, 8x4/thread)
//     Double-buffered smem, register prefetch, one sync per k-tile.
//     Fused: in-degree histogram (fire-and-forget REDs at block start),
//     epilogue a_src/a_dst per row.  (identical to the measured R9 kernel)
// ---------------------------------------------------------------------------
__global__ __launch_bounds__(256) void k_gemm(const float* __restrict__ x,
                                              const float* __restrict__ W,
                                              const float* __restrict__ att_src,
                                              const float* __restrict__ att_dst,
                                              const int* __restrict__ ei,
                                              int n, int e) {
    __shared__ float  As[2][128][17];
    __shared__ float4 Bs[2][16][16];

    const int tid  = threadIdx.x;
    const int row0 = blockIdx.x * 128;
    const int tcol = tid & 15;
    const int trow = tid >> 4;

    // ---- fused histogram: this block's slice of dst ids (REDs drain async)
    {
        int epb = (e + gridDim.x - 1) / gridDim.x;
        int e0 = blockIdx.x * epb;
        int e1 = min(e0 + epb, e);
        for (int i = e0 + tid; i < e1; i += 256)
            atomicAdd(&g_cnt[__ldg(ei + (size_t)e + i)], 1);
    }

    float acc[8][4];
#pragma unroll
    for (int i = 0; i < 8; i++)
#pragma unroll
        for (int j = 0; j < 4; j++) acc[i][j] = 0.0f;

    // ---- prologue: load k-tile 0 into buffer 0
    {
#pragma unroll
        for (int l = 0; l < 2; l++) {
            int idx = tid + l * 256;
            int r = idx >> 2, q = idx & 3;
            float4 v = make_float4(0.f, 0.f, 0.f, 0.f);
            int gr = row0 + r;
            if (gr < n)
                v = *(const float4*)(x + (size_t)gr * FIN + q * 4);
            As[0][r][q * 4 + 0] = v.x; As[0][r][q * 4 + 1] = v.y;
            As[0][r][q * 4 + 2] = v.z; As[0][r][q * 4 + 3] = v.w;
        }
        int k = tid >> 4, cq = tid & 15;
        Bs[0][k][cq] = *(const float4*)(W + (size_t)k * FOUT + cq * 4);
    }
    __syncthreads();

    int buf = 0;
    for (int k0 = 0; k0 < FIN; k0 += 16) {
        const bool has_next = (k0 + 16) < FIN;
        float4 pa0, pa1, pbv;
        if (has_next) {
            const int k1 = k0 + 16;
            {
                int r = tid >> 2, q = tid & 3;
                int gr = row0 + r;
                pa0 = (gr < n) ? *(const float4*)(x + (size_t)gr * FIN + k1 + q * 4)
                               : make_float4(0.f, 0.f, 0.f, 0.f);
            }
            {
                int idx = tid + 256;
                int r = idx >> 2, q = idx & 3;
                int gr = row0 + r;
                pa1 = (gr < n) ? *(const float4*)(x + (size_t)gr * FIN + k1 + q * 4)
                               : make_float4(0.f, 0.f, 0.f, 0.f);
            }
            {
                int k = tid >> 4, cq = tid & 15;
                pbv = *(const float4*)(W + (size_t)(k1 + k) * FOUT + cq * 4);
            }
        }

#pragma unroll
        for (int kk = 0; kk < 16; kk++) {
            float4 b = Bs[buf][kk][tcol];
#pragma unroll
            for (int i = 0; i < 8; i++) {
                float a = As[buf][trow + 16 * i][kk];
                acc[i][0] += a * b.x;
                acc[i][1] += a * b.y;
                acc[i][2] += a * b.z;
                acc[i][3] += a * b.w;
            }
        }

        if (has_next) {
            int nb = buf ^ 1;
            {
                int r = tid >> 2, q = tid & 3;
                As[nb][r][q * 4 + 0] = pa0.x; As[nb][r][q * 4 + 1] = pa0.y;
                As[nb][r][q * 4 + 2] = pa0.z; As[nb][r][q * 4 + 3] = pa0.w;
            }
            {
                int idx = tid + 256;
                int r = idx >> 2, q = idx & 3;
                As[nb][r][q * 4 + 0] = pa1.x; As[nb][r][q * 4 + 1] = pa1.y;
                As[nb][r][q * 4 + 2] = pa1.z; As[nb][r][q * 4 + 3] = pa1.w;
            }
            {
                int k = tid >> 4, cq = tid & 15;
                Bs[nb][k][cq] = pbv;
            }
            __syncthreads();
            buf = nb;
        }
    }

    const float4 asv = *(const float4*)(att_src + tcol * 4);
    const float4 adv = *(const float4*)(att_dst + tcol * 4);

#pragma unroll
    for (int i = 0; i < 8; i++) {
        int r = row0 + trow + 16 * i;
        float sa = acc[i][0] * asv.x + acc[i][1] * asv.y
                 + acc[i][2] * asv.z + acc[i][3] * asv.w;
        float sd = acc[i][0] * adv.x + acc[i][1] * adv.y
                 + acc[i][2] * adv.z + acc[i][3] * adv.w;
#pragma unroll
        for (int o = 8; o > 0; o >>= 1) {
            sa += __shfl_xor_sync(0xFFFFFFFFu, sa, o);
            sd += __shfl_xor_sync(0xFFFFFFFFu, sd, o);
        }
        if (r < n) {
            *(float4*)(g_h + (size_t)r * FOUT + tcol * 4) =
                make_float4(acc[i][0], acc[i][1], acc[i][2], acc[i][3]);
            if (tcol == 0) {
                g_as[r] = sa;
                g_ad[r] = sd;
            }
        }
    }
}

// ---------------------------------------------------------------------------
// K2a/b/c: exclusive prefix scan over cnt -> offs
// ---------------------------------------------------------------------------
__global__ __launch_bounds__(256) void k_scan1(int n) {
    __shared__ int sh[256];
    int i = blockIdx.x * 256 + threadIdx.x;
    int v = (i < n) ? g_cnt[i] : 0;
    sh[threadIdx.x] = v;
    __syncthreads();
#pragma unroll
    for (int o = 1; o < 256; o <<= 1) {
        int t = (threadIdx.x >= o) ? sh[threadIdx.x - o] : 0;
        __syncthreads();
        sh[threadIdx.x] += t;
        __syncthreads();
    }
    if (i < n) g_offs[i] = sh[threadIdx.x] - v;        // exclusive
    if (threadIdx.x == 255) g_bsum[blockIdx.x] = sh[255];
}

__global__ __launch_bounds__(512) void k_scan2(int nb) {
    __shared__ int sh[512];
    int t = threadIdx.x;
    int v = (t < nb) ? g_bsum[t] : 0;
    sh[t] = v;
    __syncthreads();
#pragma unroll
    for (int o = 1; o < 512; o <<= 1) {
        int u = (t >= o) ? sh[t - o] : 0;
        __syncthreads();
        sh[t] += u;
        __syncthreads();
    }
    if (t < nb) g_bsum[t] = sh[t] - v;                  // exclusive
}

__global__ __launch_bounds__(256) void k_scan3(int n) {
    int i = blockIdx.x * 256 + threadIdx.x;
    if (i < n) g_offs[i] += g_bsum[blockIdx.x];
}

// ---------------------------------------------------------------------------
// K3: scatter — dst-sorted packed (src, p); advances offs[d] to end.
// ---------------------------------------------------------------------------
__global__ __launch_bounds__(256) void k_scatter(const int* __restrict__ ei, int e) {
    int i = blockIdx.x * 256 + threadIdx.x;
    if (i >= e) return;
    int s = __ldg(ei + i);
    int d = __ldg(ei + e + i);
    float p = __expf(leaky(__ldg(&g_as[s]) + __ldg(&g_ad[d])));
    int pos = atomicAdd(&g_offs[d], 1);
    g_sp[pos] = make_float2(__int_as_float(s), p);
}

// ---------------------------------------------------------------------------
// K4: warp-per-dst aggregation, 8 edges in flight per warp (2 subgroups x
//     unroll 4). Epilogue: self-loop + normalize + bias; single store;
//     zeroes g_cnt for the next replay's histogram.
// ---------------------------------------------------------------------------
__global__ __launch_bounds__(256) void k_agg(const float* __restrict__ bias,
                                             float* __restrict__ out, int n) {
    int node = (int)((blockIdx.x * 256u + threadIdx.x) >> 5);
    if (node >= n) return;
    int lane = threadIdx.x & 31;
    int sub  = lane & 15;
    int half = lane >> 4;

    int cnt   = g_cnt[node];
    int end   = g_offs[node];           // post-scatter end
    int start = end - cnt;
    if (lane == 0) g_cnt[node] = 0;     // reset for next replay

    float4 acc = make_float4(0.f, 0.f, 0.f, 0.f);
    float denl = 0.0f;

    int base = start;
    for (; base + 8 <= end; base += 8) {
        int i0 = base + half;
        float2 sp0 = __ldg(&g_sp[i0]);
        float2 sp1 = __ldg(&g_sp[i0 + 2]);
        float2 sp2 = __ldg(&g_sp[i0 + 4]);
        float2 sp3 = __ldg(&g_sp[i0 + 6]);
        const float4 h0 = *(const float4*)(g_h + (size_t)__float_as_int(sp0.x) * FOUT + sub * 4);
        const float4 h1 = *(const float4*)(g_h + (size_t)__float_as_int(sp1.x) * FOUT + sub * 4);
        const float4 h2 = *(const float4*)(g_h + (size_t)__float_as_int(sp2.x) * FOUT + sub * 4);
        const float4 h3 = *(const float4*)(g_h + (size_t)__float_as_int(sp3.x) * FOUT + sub * 4);
        acc.x += sp0.y * h0.x + sp1.y * h1.x + sp2.y * h2.x + sp3.y * h3.x;
        acc.y += sp0.y * h0.y + sp1.y * h1.y + sp2.y * h2.y + sp3.y * h3.y;
        acc.z += sp0.y * h0.z + sp1.y * h1.z + sp2.y * h2.z + sp3.y * h3.z;
        acc.w += sp0.y * h0.w + sp1.y * h1.w + sp2.y * h2.w + sp3.y * h3.w;
        if (sub == 0) denl += (sp0.y + sp1.y) + (sp2.y + sp3.y);
    }
    for (; base < end; base += 2) {
        int i0 = base + half;
        if (i0 < end) {
            float2 sp0 = __ldg(&g_sp[i0]);
            const float4 h0 = *(const float4*)(g_h + (size_t)__float_as_int(sp0.x) * FOUT + sub * 4);
            acc.x += sp0.y * h0.x;
            acc.y += sp0.y * h0.y;
            acc.z += sp0.y * h0.z;
            acc.w += sp0.y * h0.w;
            if (sub == 0) denl += sp0.y;
        }
    }

    // combine the two 16-lane subgroups
    acc.x += __shfl_xor_sync(0xFFFFFFFFu, acc.x, 16);
    acc.y += __shfl_xor_sync(0xFFFFFFFFu, acc.y, 16);
    acc.z += __shfl_xor_sync(0xFFFFFFFFu, acc.z, 16);
    acc.w += __shfl_xor_sync(0xFFFFFFFFu, acc.w, 16);
    float den = __shfl_sync(0xFFFFFFFFu, denl, 0)
              + __shfl_sync(0xFFFFFFFFu, denl, 16);

    float ps  = __expf(leaky(g_as[node] + g_ad[node]));   // self-loop weight
    float inv = 1.0f / (den + ps + 1e-16f);

    if (lane < 16) {
        const float4 hi4 = *(const float4*)(g_h + (size_t)node * FOUT + sub * 4);
        const float4 b4  = *(const float4*)(bias + sub * 4);
        float4 o;
        o.x = (acc.x + ps * hi4.x) * inv + b4.x;
        o.y = (acc.y + ps * hi4.y) * inv + b4.y;
        o.z = (acc.z + ps * hi4.z) * inv + b4.z;
        o.w = (acc.w + ps * hi4.w) * inv + b4.w;
        *(float4*)(out + (size_t)node * FOUT + sub * 4) = o;
    }
}

// ---------------------------------------------------------------------------
extern "C" void kernel_launch(void* const* d_in, const int* in_sizes, int n_in,
                              void* d_out, int out_size) {
    const float* x       = (const float*)d_in[0];
    const int*   ei      = (const int*)d_in[1];
    const float* W       = (const float*)d_in[2];
    const float* att_src = (const float*)d_in[3];
    const float* att_dst = (const float*)d_in[4];
    const float* bias    = (const float*)d_in[5];
    float* out = (float*)d_out;

    const int n = in_sizes[0] / FIN;   // 100000
    const int e = in_sizes[1] / 2;     // 3200000
    const int nb = (n + 255) / 256;    // scan blocks (391 <= 512)

    // K1: projection + attention halves + fused in-degree histogram
    k_gemm<<<(n + 127) / 128, 256>>>(x, W, att_src, att_dst, ei, n, e);
    // K2: exclusive scan cnt -> offs
    k_scan1<<<nb, 256>>>(n);
    k_scan2<<<1, 512>>>(nb);
    k_scan3<<<nb, 256>>>(n);
    // K3: dst-sorted scatter of packed (src, p)
    k_scatter<<<(e + 255) / 256, 256>>>(ei, e);
    // K4: warp-per-dst aggregation (+normalize, self-loop, bias, cnt reset)
    k_agg<<<(n + 7) / 8, 256>>>(bias, out, n);
}

// round 15
// speedup vs baseline: 1.9278x; 1.8976x over previous
#include <cuda_runtime.h>
#include <cuda_bf16.h>

#define MAXN 100000
#define MAXE 3200000
#define FIN  256
#define FOUT 64

// Scratch (device globals — allocation is forbidden)
__device__ float g_h[MAXN * FOUT];     // projected features (25.6 MB, L2-resident)
__device__ float g_as[MAXN];           // h · att_src
__device__ float g_ad[MAXN];           // h · att_dst
__device__ int   g_cnt[MAXN];          // in-degree (real edges)
__device__ int   g_offs[MAXN];         // CSR offsets
__device__ int   g_bsum[512];          // scan block sums
__device__ int   g_src[MAXE];          // dst-sorted source ids
__device__ float g_p[MAXE];            // dst-sorted unnormalized softmax weights

static __device__ __forceinline__ float leaky(float v) {
    return v > 0.0f ? v : 0.2f * v;
}

// ---------------------------------------------------------------------------
// K0: zero in-degree counters (must precede gemm's fused histogram)
// ---------------------------------------------------------------------------
__global__ __launch_bounds__(256) void k_zero(int n) {
    int i = blockIdx.x * 256 + threadIdx.x;
    if (i < n) g_cnt[i] = 0;
}

// ---------------------------------------------------------------------------
// K1: h = x @ W  (SGEMM, BM=128, BN=64, BK=16, 8x4/thread) using packed
//     fma.rn.f32x2: A-tile transposed in smem (AsT[kk][row], stride 138),
//     row-pairs loaded as LDS.64 into u64, b columns broadcast-packed.
//     Inner loop: 25 instr/kk vs 41 scalar. Per-lane math = IEEE fp32.
//     Double-buffered, register prefetch. Fused: in-degree histogram,
//     epilogue a_src/a_dst per row.
// ---------------------------------------------------------------------------
__global__ __launch_bounds__(256) void k_gemm(const float* __restrict__ x,
                                              const float* __restrict__ W,
                                              const float* __restrict__ att_src,
                                              const float* __restrict__ att_dst,
                                              const int* __restrict__ ei,
                                              int n, int e) {
    __shared__ float  AsT[2][16][138];   // [buf][kk][row], stride 138 (even,
                                         // 8B-align LDS64; fill STS spans banks)
    __shared__ float4 Bs[2][16][16];

    const int tid  = threadIdx.x;
    const int row0 = blockIdx.x * 128;
    const int tcol = tid & 15;
    const int trow = tid >> 4;           // thread owns rows trow*8 .. trow*8+7

    // ---- fused histogram: this block's slice of dst ids (REDs drain async)
    {
        int epb = (e + gridDim.x - 1) / gridDim.x;
        int e0 = blockIdx.x * epb;
        int e1 = min(e0 + epb, e);
        for (int i = e0 + tid; i < e1; i += 256)
            atomicAdd(&g_cnt[__ldg(ei + (size_t)e + i)], 1);
    }

    // packed accumulators: accP[pi][j] holds rows (trow*8+2pi, trow*8+2pi+1), col j
    unsigned long long accP[4][4];
#pragma unroll
    for (int pi = 0; pi < 4; pi++)
#pragma unroll
        for (int j = 0; j < 4; j++) accP[pi][j] = 0ull;

    // ---- prologue: load k-tile 0 into buffer 0
    {
#pragma unroll
        for (int l = 0; l < 2; l++) {
            int idx = tid + l * 256;
            int r = idx >> 2, q = idx & 3;
            float4 v = make_float4(0.f, 0.f, 0.f, 0.f);
            int gr = row0 + r;
            if (gr < n)
                v = *(const float4*)(x + (size_t)gr * FIN + q * 4);
            AsT[0][q * 4 + 0][r] = v.x; AsT[0][q * 4 + 1][r] = v.y;
            AsT[0][q * 4 + 2][r] = v.z; AsT[0][q * 4 + 3][r] = v.w;
        }
        int k = tid >> 4, cq = tid & 15;
        Bs[0][k][cq] = *(const float4*)(W + (size_t)k * FOUT + cq * 4);
    }
    __syncthreads();

    int buf = 0;
    for (int k0 = 0; k0 < FIN; k0 += 16) {
        const bool has_next = (k0 + 16) < FIN;
        float4 pa0, pa1, pbv;
        if (has_next) {
            const int k1 = k0 + 16;
            {
                int r = tid >> 2, q = tid & 3;
                int gr = row0 + r;
                pa0 = (gr < n) ? *(const float4*)(x + (size_t)gr * FIN + k1 + q * 4)
                               : make_float4(0.f, 0.f, 0.f, 0.f);
            }
            {
                int idx = tid + 256;
                int r = idx >> 2, q = idx & 3;
                int gr = row0 + r;
                pa1 = (gr < n) ? *(const float4*)(x + (size_t)gr * FIN + k1 + q * 4)
                               : make_float4(0.f, 0.f, 0.f, 0.f);
            }
            {
                int k = tid >> 4, cq = tid & 15;
                pbv = *(const float4*)(W + (size_t)(k1 + k) * FOUT + cq * 4);
            }
        }

        // ---- packed-f32x2 mainloop over this k-tile
        const int rowbase = trow * 8;
#pragma unroll
        for (int kk = 0; kk < 16; kk++) {
            float4 b = Bs[buf][kk][tcol];
            unsigned long long bb0, bb1, bb2, bb3;
            asm("mov.b64 %0, {%1, %1};" : "=l"(bb0) : "f"(b.x));
            asm("mov.b64 %0, {%1, %1};" : "=l"(bb1) : "f"(b.y));
            asm("mov.b64 %0, {%1, %1};" : "=l"(bb2) : "f"(b.z));
            asm("mov.b64 %0, {%1, %1};" : "=l"(bb3) : "f"(b.w));
#pragma unroll
            for (int pi = 0; pi < 4; pi++) {
                unsigned long long aa =
                    *(const unsigned long long*)&AsT[buf][kk][rowbase + 2 * pi];
                asm("fma.rn.f32x2 %0, %1, %2, %0;" : "+l"(accP[pi][0])
                    : "l"(aa), "l"(bb0));
                asm("fma.rn.f32x2 %0, %1, %2, %0;" : "+l"(accP[pi][1])
                    : "l"(aa), "l"(bb1));
                asm("fma.rn.f32x2 %0, %1, %2, %0;" : "+l"(accP[pi][2])
                    : "l"(aa), "l"(bb2));
                asm("fma.rn.f32x2 %0, %1, %2, %0;" : "+l"(accP[pi][3])
                    : "l"(aa), "l"(bb3));
            }
        }

        if (has_next) {
            int nb = buf ^ 1;
            {
                int r = tid >> 2, q = tid & 3;
                AsT[nb][q * 4 + 0][r] = pa0.x; AsT[nb][q * 4 + 1][r] = pa0.y;
                AsT[nb][q * 4 + 2][r] = pa0.z; AsT[nb][q * 4 + 3][r] = pa0.w;
            }
            {
                int idx = tid + 256;
                int r = idx >> 2, q = idx & 3;
                AsT[nb][q * 4 + 0][r] = pa1.x; AsT[nb][q * 4 + 1][r] = pa1.y;
                AsT[nb][q * 4 + 2][r] = pa1.z; AsT[nb][q * 4 + 3][r] = pa1.w;
            }
            {
                int k = tid >> 4, cq = tid & 15;
                Bs[nb][k][cq] = pbv;
            }
            __syncthreads();
            buf = nb;
        }
    }

    // ---- unpack packed accumulators to per-row acc[8][4]
    float acc[8][4];
#pragma unroll
    for (int pi = 0; pi < 4; pi++)
#pragma unroll
        for (int j = 0; j < 4; j++) {
            float lo, hi;
            asm("mov.b64 {%0, %1}, %2;" : "=f"(lo), "=f"(hi) : "l"(accP[pi][j]));
            acc[2 * pi][j]     = lo;
            acc[2 * pi + 1][j] = hi;
        }

    const float4 asv = *(const float4*)(att_src + tcol * 4);
    const float4 adv = *(const float4*)(att_dst + tcol * 4);

#pragma unroll
    for (int i = 0; i < 8; i++) {
        int r = row0 + trow * 8 + i;
        float sa = acc[i][0] * asv.x + acc[i][1] * asv.y
                 + acc[i][2] * asv.z + acc[i][3] * asv.w;
        float sd = acc[i][0] * adv.x + acc[i][1] * adv.y
                 + acc[i][2] * adv.z + acc[i][3] * adv.w;
#pragma unroll
        for (int o = 8; o > 0; o >>= 1) {
            sa += __shfl_xor_sync(0xFFFFFFFFu, sa, o);
            sd += __shfl_xor_sync(0xFFFFFFFFu, sd, o);
        }
        if (r < n) {
            *(float4*)(g_h + (size_t)r * FOUT + tcol * 4) =
                make_float4(acc[i][0], acc[i][1], acc[i][2], acc[i][3]);
            if (tcol == 0) {
                g_as[r] = sa;
                g_ad[r] = sd;
            }
        }
    }
}

// ---------------------------------------------------------------------------
// K2a/b/c: exclusive prefix scan over cnt -> offs
// ---------------------------------------------------------------------------
__global__ __launch_bounds__(256) void k_scan1(int n) {
    __shared__ int sh[256];
    int i = blockIdx.x * 256 + threadIdx.x;
    int v = (i < n) ? g_cnt[i] : 0;
    sh[threadIdx.x] = v;
    __syncthreads();
#pragma unroll
    for (int o = 1; o < 256; o <<= 1) {
        int t = (threadIdx.x >= o) ? sh[threadIdx.x - o] : 0;
        __syncthreads();
        sh[threadIdx.x] += t;
        __syncthreads();
    }
    if (i < n) g_offs[i] = sh[threadIdx.x] - v;        // exclusive
    if (threadIdx.x == 255) g_bsum[blockIdx.x] = sh[255];
}

__global__ __launch_bounds__(512) void k_scan2(int nb) {
    __shared__ int sh[512];
    int t = threadIdx.x;
    int v = (t < nb) ? g_bsum[t] : 0;
    sh[t] = v;
    __syncthreads();
#pragma unroll
    for (int o = 1; o < 512; o <<= 1) {
        int u = (t >= o) ? sh[t - o] : 0;
        __syncthreads();
        sh[t] += u;
        __syncthreads();
    }
    if (t < nb) g_bsum[t] = sh[t] - v;                  // exclusive
}

__global__ __launch_bounds__(256) void k_scan3(int n) {
    int i = blockIdx.x * 256 + threadIdx.x;
    if (i < n) g_offs[i] += g_bsum[blockIdx.x];
}

// ---------------------------------------------------------------------------
// K3: scatter — dst-sorted (src, p) pairs; p = exp(leakyrelu(as[s]+ad[d])).
//     Advances offs[d] to its end; agg recovers start = end - cnt.
// ---------------------------------------------------------------------------
__global__ __launch_bounds__(256) void k_scatter(const int* __restrict__ ei, int e) {
    int i = blockIdx.x * 256 + threadIdx.x;
    if (i >= e) return;
    int s = __ldg(ei + i);
    int d = __ldg(ei + e + i);
    float p = __expf(leaky(__ldg(&g_as[s]) + __ldg(&g_ad[d])));
    int pos = atomicAdd(&g_offs[d], 1);
    g_src[pos] = s;
    g_p[pos]   = p;
}

// ---------------------------------------------------------------------------
// K4: warp-per-dst aggregation, 4 edges in flight per warp (2 subgroups x
//     unroll 2). Epilogue: self-loop + normalize + bias; single store.
// ---------------------------------------------------------------------------
__global__ __launch_bounds__(256) void k_agg(const float* __restrict__ bias,
                                             float* __restrict__ out, int n) {
    int node = (int)((blockIdx.x * 256u + threadIdx.x) >> 5);
    if (node >= n) return;
    int lane = threadIdx.x & 31;
    int sub  = lane & 15;
    int half = lane >> 4;               // 0 or 1

    int end   = g_offs[node];           // post-scatter end
    int start = end - g_cnt[node];

    float4 acc = make_float4(0.f, 0.f, 0.f, 0.f);
    float denl = 0.0f;

    int base = start;
    for (; base + 4 <= end; base += 4) {
        int i0 = base + half;
        int i1 = i0 + 2;
        int   s0 = __ldg(&g_src[i0]);
        int   s1 = __ldg(&g_src[i1]);
        float p0 = __ldg(&g_p[i0]);
        float p1 = __ldg(&g_p[i1]);
        const float4 h0 = *(const float4*)(g_h + (size_t)s0 * FOUT + sub * 4);
        const float4 h1 = *(const float4*)(g_h + (size_t)s1 * FOUT + sub * 4);
        acc.x += p0 * h0.x + p1 * h1.x;
        acc.y += p0 * h0.y + p1 * h1.y;
        acc.z += p0 * h0.z + p1 * h1.z;
        acc.w += p0 * h0.w + p1 * h1.w;
        if (sub == 0) denl += p0 + p1;
    }
    for (; base < end; base += 2) {
        int i0 = base + half;
        if (i0 < end) {
            int   s0 = __ldg(&g_src[i0]);
            float p0 = __ldg(&g_p[i0]);
            const float4 h0 = *(const float4*)(g_h + (size_t)s0 * FOUT + sub * 4);
            acc.x += p0 * h0.x;
            acc.y += p0 * h0.y;
            acc.z += p0 * h0.z;
            acc.w += p0 * h0.w;
            if (sub == 0) denl += p0;
        }
    }

    // combine the two 16-lane subgroups
    acc.x += __shfl_xor_sync(0xFFFFFFFFu, acc.x, 16);
    acc.y += __shfl_xor_sync(0xFFFFFFFFu, acc.y, 16);
    acc.z += __shfl_xor_sync(0xFFFFFFFFu, acc.z, 16);
    acc.w += __shfl_xor_sync(0xFFFFFFFFu, acc.w, 16);
    float den = __shfl_sync(0xFFFFFFFFu, denl, 0)
              + __shfl_sync(0xFFFFFFFFu, denl, 16);

    float ps  = __expf(leaky(g_as[node] + g_ad[node]));   // self-loop weight
    float inv = 1.0f / (den + ps + 1e-16f);

    if (lane < 16) {
        const float4 hi4 = *(const float4*)(g_h + (size_t)node * FOUT + sub * 4);
        const float4 b4  = *(const float4*)(bias + sub * 4);
        float4 o;
        o.x = (acc.x + ps * hi4.x) * inv + b4.x;
        o.y = (acc.y + ps * hi4.y) * inv + b4.y;
        o.z = (acc.z + ps * hi4.z) * inv + b4.z;
        o.w = (acc.w + ps * hi4.w) * inv + b4.w;
        *(float4*)(out + (size_t)node * FOUT + sub * 4) = o;
    }
}

// ---------------------------------------------------------------------------
extern "C" void kernel_launch(void* const* d_in, const int* in_sizes, int n_in,
                              void* d_out, int out_size) {
    const float* x       = (const float*)d_in[0];
    const int*   ei      = (const int*)d_in[1];
    const float* W       = (const float*)d_in[2];
    const float* att_src = (const float*)d_in[3];
    const float* att_dst = (const float*)d_in[4];
    const float* bias    = (const float*)d_in[5];
    float* out = (float*)d_out;

    const int n = in_sizes[0] / FIN;   // 100000
    const int e = in_sizes[1] / 2;     // 3200000
    const int nb = (n + 255) / 256;    // scan blocks (391 <= 512)

    // K0: zero counters (before gemm's fused histogram)
    k_zero<<<nb, 256>>>(n);
    // K1: projection (f32x2-packed) + attention halves + fused histogram
    k_gemm<<<(n + 127) / 128, 256>>>(x, W, att_src, att_dst, ei, n, e);
    // K2: exclusive scan cnt -> offs
    k_scan1<<<nb, 256>>>(n);
    k_scan2<<<1, 512>>>(nb);
    k_scan3<<<nb, 256>>>(n);
    // K3: dst-sorted scatter of (src, p)
    k_scatter<<<(e + 255) / 256, 256>>>(ei, e);
    // K4: warp-per-dst aggregation (+softmax normalize, self-loop, bias)
    k_agg<<<(n + 7) / 8, 256>>>(bias, out, n);
}